// round 2
// baseline (speedup 1.0000x reference)
#include <cuda_runtime.h>
#include <cstdint>

// Problem constants: q/k/v [4,8,128,128,64] f32, mask [4,1,128,128,128] i32.
#define NPROB 4096      // B*H*N
#define Ldim 128
#define Ddim 64

// ---------------- packed f32x2 helpers (Blackwell FFMA2 path) ----------------
static __device__ __forceinline__ unsigned long long ffma2(
    unsigned long long a, unsigned long long b, unsigned long long c) {
    unsigned long long d;
    asm("fma.rn.f32x2 %0, %1, %2, %3;" : "=l"(d) : "l"(a), "l"(b), "l"(c));
    return d;
}
static __device__ __forceinline__ unsigned long long pack2(float lo, float hi) {
    unsigned long long r;
    asm("mov.b64 %0, {%1, %2};" : "=l"(r) : "f"(lo), "f"(hi));
    return r;
}
static __device__ __forceinline__ float2 unpack2(unsigned long long p) {
    float2 f;
    asm("mov.b64 {%0, %1}, %2;" : "=f"(f.x), "=f"(f.y) : "l"(p));
    return f;
}

// ---------------- smem layout (bytes) ----------------
// Kt:  [0, 64*132*4)              = 33792   K transposed, row stride 132 f32 (16B aligned)
// Qs:  [33792, 33792 + 128*65*4)  = +33280  -> 67072 (row stride 65: conflict-free column reads)
// Ps:  overlays [0, 128*129*4=66048)        (written only after sync; Kt/Qs dead)
// Vs:  [67072, 67072 + 128*64*4)  = 99840
#define KT_OFF 0
#define QS_OFF 33792
#define VS_OFF 67072
#define SMEM_BYTES 99840
#define KT_STRIDE 132
#define QS_STRIDE 65
#define PS_STRIDE 129

__global__ void __launch_bounds__(128)
attn_kernel(const float* __restrict__ q, const float* __restrict__ k,
            const float* __restrict__ v, const int* __restrict__ mask,
            float* __restrict__ out)
{
    extern __shared__ char smem[];
    float* Kt = (float*)(smem + KT_OFF);
    float* Qs = (float*)(smem + QS_OFF);
    float* Ps = (float*)(smem + KT_OFF);   // overlay
    float* Vs = (float*)(smem + VS_OFF);

    const int tid = threadIdx.x;
    const int blk = blockIdx.x;
    const size_t base = (size_t)blk * (Ldim * Ddim);

    // ---- cooperative loads: Q (to padded smem), K (transposed), V (natural) ----
    const float4* q4 = (const float4*)(q + base);
    const float4* k4 = (const float4*)(k + base);
    const float4* v4 = (const float4*)(v + base);
#pragma unroll
    for (int it = 0; it < 16; ++it) {
        int idx = it * 128 + tid;          // 0..2047 float4s = 8192 floats
        int row = idx >> 4;                // 0..127
        int dc  = (idx & 15) << 2;         // 0..60
        float4 tq = q4[idx];
        float* qdst = Qs + row * QS_STRIDE + dc;
        qdst[0] = tq.x; qdst[1] = tq.y; qdst[2] = tq.z; qdst[3] = tq.w;
        float4 tk = k4[idx];
        Kt[(dc + 0) * KT_STRIDE + row] = tk.x;
        Kt[(dc + 1) * KT_STRIDE + row] = tk.y;
        Kt[(dc + 2) * KT_STRIDE + row] = tk.z;
        Kt[(dc + 3) * KT_STRIDE + row] = tk.w;
        *(float4*)(Vs + row * Ddim + dc) = v4[idx];
    }
    __syncthreads();

    // ---- S = Q K^T : thread tid owns q-row tid; 2 k-cols per FFMA2 ----
    unsigned long long s[64];
#pragma unroll
    for (int i = 0; i < 64; ++i) s[i] = 0ull;

    for (int d = 0; d < Ddim; ++d) {       // runtime loop keeps code small
        float qd = Qs[tid * QS_STRIDE + d];         // conflict-free (pad 65)
        unsigned long long q2 = pack2(qd, qd);
        const ulonglong2* kt2 = (const ulonglong2*)(Kt + d * KT_STRIDE);
#pragma unroll
        for (int j4 = 0; j4 < 32; ++j4) {           // 32 x 16B = all 128 k-cols
            ulonglong2 kk = kt2[j4];
            s[2 * j4]     = ffma2(q2, kk.x, s[2 * j4]);
            s[2 * j4 + 1] = ffma2(q2, kk.y, s[2 * j4 + 1]);
        }
    }

    // ---- scale + mask + softmax, fully thread-local ----
    const int b = blk >> 10;               // blk / (H*N) = blk / 1024
    const int n = blk & (Ldim - 1);        // N == 128
    const int4* mrow = (const int4*)(mask +
        ((((size_t)b * 128) + n) * Ldim + tid) * Ldim);

    float mx = -3.0e38f;
#pragma unroll
    for (int j4 = 0; j4 < 32; ++j4) {
        int4 mm = mrow[j4];
        float2 a  = unpack2(s[2 * j4]);
        float2 bb = unpack2(s[2 * j4 + 1]);
        a.x  = (mm.x == 0) ? -32768.0f : a.x  * 0.125f;
        a.y  = (mm.y == 0) ? -32768.0f : a.y  * 0.125f;
        bb.x = (mm.z == 0) ? -32768.0f : bb.x * 0.125f;
        bb.y = (mm.w == 0) ? -32768.0f : bb.y * 0.125f;
        mx = fmaxf(mx, fmaxf(fmaxf(a.x, a.y), fmaxf(bb.x, bb.y)));
        s[2 * j4]     = pack2(a.x, a.y);
        s[2 * j4 + 1] = pack2(bb.x, bb.y);
    }
    float sum = 0.0f;
#pragma unroll
    for (int j2 = 0; j2 < 64; ++j2) {
        float2 a = unpack2(s[j2]);
        a.x = __expf(a.x - mx);            // masked -> exp(~-32770) == 0 exactly
        a.y = __expf(a.y - mx);
        sum += a.x + a.y;
        s[j2] = pack2(a.x, a.y);
    }
    float inv = 1.0f / sum;

    __syncthreads();                       // all threads done reading Kt/Qs
#pragma unroll
    for (int j2 = 0; j2 < 64; ++j2) {      // conflict-free row write (pad 129)
        float2 a = unpack2(s[j2]);
        Ps[tid * PS_STRIDE + 2 * j2]     = a.x * inv;
        Ps[tid * PS_STRIDE + 2 * j2 + 1] = a.y * inv;
    }
    __syncthreads();

    // ---- O = P V : 2 head-dims per FFMA2, V rows broadcast ----
    unsigned long long o[32];
#pragma unroll
    for (int i = 0; i < 32; ++i) o[i] = 0ull;

    for (int j = 0; j < Ldim; ++j) {       // runtime loop
        float pj = Ps[tid * PS_STRIDE + j];         // conflict-free (pad 129)
        unsigned long long p2 = pack2(pj, pj);
        const ulonglong2* vr = (const ulonglong2*)(Vs + j * Ddim);
#pragma unroll
        for (int d4 = 0; d4 < 16; ++d4) {           // 16 x 16B = full D=64 row
            ulonglong2 vv = vr[d4];
            o[2 * d4]     = ffma2(p2, vv.x, o[2 * d4]);
            o[2 * d4 + 1] = ffma2(p2, vv.y, o[2 * d4 + 1]);
        }
    }

    float4* orow = (float4*)(out + base + tid * Ddim);
#pragma unroll
    for (int d4 = 0; d4 < 16; ++d4) {
        float2 a  = unpack2(o[2 * d4]);
        float2 bb = unpack2(o[2 * d4 + 1]);
        orow[d4] = make_float4(a.x, a.y, bb.x, bb.y);
    }
}

extern "C" void kernel_launch(void* const* d_in, const int* in_sizes, int n_in,
                              void* d_out, int out_size) {
    const float* q    = (const float*)d_in[0];
    const float* k    = (const float*)d_in[1];
    const float* v    = (const float*)d_in[2];
    const int*   mask = (const int*)  d_in[3];
    float* out = (float*)d_out;

    // Opt-in smem above 48KB. Idempotent, capture-safe (not a stream op),
    // called unconditionally every launch (no static guards).
    cudaFuncSetAttribute(attn_kernel,
                         cudaFuncAttributeMaxDynamicSharedMemorySize, SMEM_BYTES);

    attn_kernel<<<NPROB, 128, SMEM_BYTES>>>(q, k, v, mask, out);
}